// round 1
// baseline (speedup 1.0000x reference)
#include <cuda_runtime.h>

#define NP 300            // X = Y = Z = 300
#define NC 16             // channels
#define PLANE_ELEMS (NP * NP)

// Channel-interleaved scratch: plane[(y*NP + x)*NC + c], line[p][pos*NC + c]
__device__ float g_t_xy[PLANE_ELEMS * NC];   // 5.76 MB
__device__ float g_t_yz[PLANE_ELEMS * NC];
__device__ float g_t_xz[PLANE_ELEMS * NC];
__device__ float g_t_line[3][NP * NC];       // 57.6 KB

// ---------------------------------------------------------------------------
// Pass 1: transpose (C, H, W) -> (H*W, C) for the three planes + three lines.
// Reads are coalesced across threads (fixed c, consecutive p); writes are
// 4x float4 per thread. Total traffic ~35 MB -> negligible.
// ---------------------------------------------------------------------------
__global__ void transpose_kernel(const float* __restrict__ pxy,
                                 const float* __restrict__ pyz,
                                 const float* __restrict__ pxz,
                                 const float* __restrict__ lx,
                                 const float* __restrict__ ly,
                                 const float* __restrict__ lz) {
    int idx = blockIdx.x * blockDim.x + threadIdx.x;
    if (idx < 3 * PLANE_ELEMS) {
        int plane = idx / PLANE_ELEMS;
        int p = idx - plane * PLANE_ELEMS;
        const float* src = (plane == 0) ? pxy : (plane == 1) ? pyz : pxz;
        float* dst = (plane == 0) ? g_t_xy : (plane == 1) ? g_t_yz : g_t_xz;
        float v[NC];
#pragma unroll
        for (int c = 0; c < NC; c++) v[c] = src[c * PLANE_ELEMS + p];
        float4* d4 = reinterpret_cast<float4*>(dst + p * NC);
        d4[0] = make_float4(v[0], v[1], v[2], v[3]);
        d4[1] = make_float4(v[4], v[5], v[6], v[7]);
        d4[2] = make_float4(v[8], v[9], v[10], v[11]);
        d4[3] = make_float4(v[12], v[13], v[14], v[15]);
    } else {
        int j = idx - 3 * PLANE_ELEMS;
        if (j < 3 * NP) {
            int l = j / NP;
            int p = j - l * NP;
            const float* src = (l == 0) ? lx : (l == 1) ? ly : lz;
            float v[NC];
#pragma unroll
            for (int c = 0; c < NC; c++) v[c] = src[c * NP + p];
            float4* d4 = reinterpret_cast<float4*>(&g_t_line[l][p * NC]);
            d4[0] = make_float4(v[0], v[1], v[2], v[3]);
            d4[1] = make_float4(v[4], v[5], v[6], v[7]);
            d4[2] = make_float4(v[8], v[9], v[10], v[11]);
            d4[3] = make_float4(v[12], v[13], v[14], v[15]);
        }
    }
}

// ---------------------------------------------------------------------------
// Pass 2: per-point tri-plane / tri-line sampling.
// ---------------------------------------------------------------------------
struct PlaneSample {
    const float4* p00;
    const float4* p01;
    const float4* p10;
    const float4* p11;
    float w00, w01, w10, w11;
};

__device__ __forceinline__ PlaneSample plane_setup(const float* t, float2 g) {
    // ix = (g+1)*0.5*(W-1), W-1 = 299 (same formula as reference)
    float ix = (g.x + 1.0f) * 0.5f * (float)(NP - 1);
    float iy = (g.y + 1.0f) * 0.5f * (float)(NP - 1);
    float fx = floorf(ix);
    float fy = floorf(iy);
    float wx = ix - fx;
    float wy = iy - fy;
    int x0 = min(max((int)fx, 0), NP - 1);
    int x1 = min(x0 + 1, NP - 1);
    int y0 = min(max((int)fy, 0), NP - 1);
    int y1 = min(y0 + 1, NP - 1);
    PlaneSample s;
    s.p00 = reinterpret_cast<const float4*>(t + (y0 * NP + x0) * NC);
    s.p01 = reinterpret_cast<const float4*>(t + (y0 * NP + x1) * NC);
    s.p10 = reinterpret_cast<const float4*>(t + (y1 * NP + x0) * NC);
    s.p11 = reinterpret_cast<const float4*>(t + (y1 * NP + x1) * NC);
    s.w00 = (1.0f - wx) * (1.0f - wy);
    s.w01 = wx * (1.0f - wy);
    s.w10 = (1.0f - wx) * wy;
    s.w11 = wx * wy;
    return s;
}

struct LineSample {
    const float4* p0;
    const float4* p1;
    float w;
};

__device__ __forceinline__ LineSample line_setup(const float* t, float gy) {
    // For lines: W=1 -> ix=0, wx=0; only the y component interpolates.
    float iy = (gy + 1.0f) * 0.5f * (float)(NP - 1);
    float fy = floorf(iy);
    float wy = iy - fy;
    int y0 = min(max((int)fy, 0), NP - 1);
    int y1 = min(y0 + 1, NP - 1);
    LineSample s;
    s.p0 = reinterpret_cast<const float4*>(t + y0 * NC);
    s.p1 = reinterpret_cast<const float4*>(t + y1 * NC);
    s.w = wy;
    return s;
}

__device__ __forceinline__ float4 blend4(const PlaneSample& s, int cc) {
    float4 a = __ldg(s.p00 + cc);
    float4 b = __ldg(s.p01 + cc);
    float4 c = __ldg(s.p10 + cc);
    float4 d = __ldg(s.p11 + cc);
    float4 r;
    r.x = a.x * s.w00 + b.x * s.w01 + c.x * s.w10 + d.x * s.w11;
    r.y = a.y * s.w00 + b.y * s.w01 + c.y * s.w10 + d.y * s.w11;
    r.z = a.z * s.w00 + b.z * s.w01 + c.z * s.w10 + d.z * s.w11;
    r.w = a.w * s.w00 + b.w * s.w01 + c.w * s.w10 + d.w * s.w11;
    return r;
}

__device__ __forceinline__ float4 lblend4(const LineSample& s, int cc) {
    float4 a = __ldg(s.p0 + cc);
    float4 b = __ldg(s.p1 + cc);
    float w1 = 1.0f - s.w;
    float4 r;
    r.x = a.x * w1 + b.x * s.w;
    r.y = a.y * w1 + b.y * s.w;
    r.z = a.z * w1 + b.z * s.w;
    r.w = a.w * w1 + b.w * s.w;
    return r;
}

__global__ __launch_bounds__(256)
void sample_kernel(const float2* __restrict__ cp,
                   const float2* __restrict__ cl,
                   float* __restrict__ out, int n) {
    int i = blockIdx.x * blockDim.x + threadIdx.x;
    if (i >= n) return;

    // coords_plane/coords_line layout: (3, N, 2) -> float2 at [p*N + i]
    float2 cp0 = cp[0 * n + i];  // -> plane_xy
    float2 cp1 = cp[1 * n + i];  // -> plane_yz
    float2 cp2 = cp[2 * n + i];  // -> plane_xz
    float2 cl0 = cl[0 * n + i];  // -> line_x
    float2 cl1 = cl[1 * n + i];  // -> line_y
    float2 cl2 = cl[2 * n + i];  // -> line_z

    PlaneSample s_xy = plane_setup(g_t_xy, cp0);
    PlaneSample s_yz = plane_setup(g_t_yz, cp1);
    PlaneSample s_xz = plane_setup(g_t_xz, cp2);
    LineSample l_x = line_setup(g_t_line[0], cl0.y);
    LineSample l_y = line_setup(g_t_line[1], cl1.y);
    LineSample l_z = line_setup(g_t_line[2], cl2.y);

    // out_x = f_yz * f_x ; out_y = f_xz * f_y ; out_z = f_xy * f_z
    float4* out_x = reinterpret_cast<float4*>(out + (size_t)0 * n * NC + (size_t)i * NC);
    float4* out_y = reinterpret_cast<float4*>(out + (size_t)1 * n * NC + (size_t)i * NC);
    float4* out_z = reinterpret_cast<float4*>(out + (size_t)2 * n * NC + (size_t)i * NC);

#pragma unroll
    for (int cc = 0; cc < NC / 4; cc++) {
        float4 fyz = blend4(s_yz, cc);
        float4 fxz = blend4(s_xz, cc);
        float4 fxy = blend4(s_xy, cc);
        float4 fx = lblend4(l_x, cc);
        float4 fy = lblend4(l_y, cc);
        float4 fz = lblend4(l_z, cc);
        out_x[cc] = make_float4(fyz.x * fx.x, fyz.y * fx.y, fyz.z * fx.z, fyz.w * fx.w);
        out_y[cc] = make_float4(fxz.x * fy.x, fxz.y * fy.y, fxz.z * fy.z, fxz.w * fy.w);
        out_z[cc] = make_float4(fxy.x * fz.x, fxy.y * fz.y, fxy.z * fz.z, fxy.w * fz.w);
    }
}

extern "C" void kernel_launch(void* const* d_in, const int* in_sizes, int n_in,
                              void* d_out, int out_size) {
    const float* coords_plane = (const float*)d_in[0];
    const float* coords_line  = (const float*)d_in[1];
    const float* plane_xy     = (const float*)d_in[2];
    const float* plane_yz     = (const float*)d_in[3];
    const float* plane_xz     = (const float*)d_in[4];
    const float* line_x       = (const float*)d_in[5];
    const float* line_y       = (const float*)d_in[6];
    const float* line_z       = (const float*)d_in[7];

    int n = in_sizes[0] / 6;  // coords_plane has 3*N*2 elements

    int t_total = 3 * PLANE_ELEMS + 3 * NP;
    transpose_kernel<<<(t_total + 255) / 256, 256>>>(plane_xy, plane_yz, plane_xz,
                                                     line_x, line_y, line_z);

    sample_kernel<<<(n + 255) / 256, 256>>>(
        (const float2*)coords_plane, (const float2*)coords_line,
        (float*)d_out, n);
}

// round 2
// speedup vs baseline: 2.1839x; 2.1839x over previous
#include <cuda_runtime.h>
#include <cuda_fp16.h>

#define NP 300            // X = Y = Z = 300
#define NC 16             // channels
#define PLANE_ELEMS (NP * NP)

// Channel-interleaved scratch.
// Planes in fp16: corner = 32 B (1 L2 sector). 3 x 2.88 MB = 8.6 MB (L2-resident).
// Lines in fp32 (tiny, L1-resident) so each output has only ONE quantized factor.
__device__ __half g_p[3][PLANE_ELEMS * NC];   // [0]=xy, [1]=yz, [2]=xz
__device__ float  g_l[3][NP * NC];            // [0]=x,  [1]=y,  [2]=z

// ---------------------------------------------------------------------------
// Pass 1: transpose (C, H, W) -> (H*W, C), planes converted to fp16.
// ---------------------------------------------------------------------------
__global__ void transpose_kernel(const float* __restrict__ pxy,
                                 const float* __restrict__ pyz,
                                 const float* __restrict__ pxz,
                                 const float* __restrict__ lx,
                                 const float* __restrict__ ly,
                                 const float* __restrict__ lz) {
    int idx = blockIdx.x * blockDim.x + threadIdx.x;
    if (idx < 3 * PLANE_ELEMS) {
        int plane = idx / PLANE_ELEMS;
        int p = idx - plane * PLANE_ELEMS;
        const float* src = (plane == 0) ? pxy : (plane == 1) ? pyz : pxz;
        __half2 h[NC / 2];
#pragma unroll
        for (int c = 0; c < NC / 2; c++) {
            h[c] = __floats2half2_rn(src[(2 * c) * PLANE_ELEMS + p],
                                     src[(2 * c + 1) * PLANE_ELEMS + p]);
        }
        // 16 halves = 32 B = 2 x uint4
        uint4* d = reinterpret_cast<uint4*>(&g_p[plane][p * NC]);
        const uint4* s = reinterpret_cast<const uint4*>(h);
        d[0] = s[0];
        d[1] = s[1];
    } else {
        int j = idx - 3 * PLANE_ELEMS;
        if (j < 3 * NP) {
            int l = j / NP;
            int p = j - l * NP;
            const float* src = (l == 0) ? lx : (l == 1) ? ly : lz;
            float v[NC];
#pragma unroll
            for (int c = 0; c < NC; c++) v[c] = src[c * NP + p];
            float4* d4 = reinterpret_cast<float4*>(&g_l[l][p * NC]);
            d4[0] = make_float4(v[0], v[1], v[2], v[3]);
            d4[1] = make_float4(v[4], v[5], v[6], v[7]);
            d4[2] = make_float4(v[8], v[9], v[10], v[11]);
            d4[3] = make_float4(v[12], v[13], v[14], v[15]);
        }
    }
}

// ---------------------------------------------------------------------------
// Pass 2: quad-cooperative sampling. 4 lanes per point; lane `sub` owns
// channels [4*sub, 4*sub+4). Quad lanes read contiguous bytes of each corner,
// so warp gather wavefronts drop ~4x vs one-thread-per-point.
// ---------------------------------------------------------------------------
__device__ __forceinline__ float4 ldh4(const __half* p) {
    uint2 r = __ldg(reinterpret_cast<const uint2*>(p));
    __half2 a = *reinterpret_cast<__half2*>(&r.x);
    __half2 b = *reinterpret_cast<__half2*>(&r.y);
    float2 fa = __half22float2(a);
    float2 fb = __half22float2(b);
    return make_float4(fa.x, fa.y, fb.x, fb.y);
}

__device__ __forceinline__ float4 plane_fetch(const __half* __restrict__ tbl,
                                              float2 g, int sub) {
    float ix = (g.x + 1.0f) * 0.5f * (float)(NP - 1);
    float iy = (g.y + 1.0f) * 0.5f * (float)(NP - 1);
    float fx = floorf(ix);
    float fy = floorf(iy);
    float wx = ix - fx;
    float wy = iy - fy;
    int x0 = min(max((int)fx, 0), NP - 1);
    int x1 = min(x0 + 1, NP - 1);
    int y0 = min(max((int)fy, 0), NP - 1);
    int y1 = min(y0 + 1, NP - 1);
    float w00 = (1.0f - wx) * (1.0f - wy);
    float w01 = wx * (1.0f - wy);
    float w10 = (1.0f - wx) * wy;
    float w11 = wx * wy;
    int co = sub * 4;
    float4 a = ldh4(tbl + (y0 * NP + x0) * NC + co);
    float4 b = ldh4(tbl + (y0 * NP + x1) * NC + co);
    float4 c = ldh4(tbl + (y1 * NP + x0) * NC + co);
    float4 d = ldh4(tbl + (y1 * NP + x1) * NC + co);
    float4 r;
    r.x = a.x * w00 + b.x * w01 + c.x * w10 + d.x * w11;
    r.y = a.y * w00 + b.y * w01 + c.y * w10 + d.y * w11;
    r.z = a.z * w00 + b.z * w01 + c.z * w10 + d.z * w11;
    r.w = a.w * w00 + b.w * w01 + c.w * w10 + d.w * w11;
    return r;
}

__device__ __forceinline__ float4 line_fetch(const float* __restrict__ tbl,
                                             float gy, int sub) {
    float iy = (gy + 1.0f) * 0.5f * (float)(NP - 1);
    float fy = floorf(iy);
    float wy = iy - fy;
    int y0 = min(max((int)fy, 0), NP - 1);
    int y1 = min(y0 + 1, NP - 1);
    int co = sub * 4;
    float4 a = __ldg(reinterpret_cast<const float4*>(tbl + y0 * NC + co));
    float4 b = __ldg(reinterpret_cast<const float4*>(tbl + y1 * NC + co));
    float w1 = 1.0f - wy;
    float4 r;
    r.x = a.x * w1 + b.x * wy;
    r.y = a.y * w1 + b.y * wy;
    r.z = a.z * w1 + b.z * wy;
    r.w = a.w * w1 + b.w * wy;
    return r;
}

__global__ __launch_bounds__(256)
void sample_kernel(const float2* __restrict__ cp,
                   const float2* __restrict__ cl,
                   float* __restrict__ out, int n) {
    int t = blockIdx.x * blockDim.x + threadIdx.x;
    int sub = t & 3;          // channel quad within point
    int i = t >> 2;           // point index
    if (i >= n) return;

    // Quad lanes read the SAME coord addresses (broadcast-coalesced).
    float2 cp0 = __ldg(&cp[0 * n + i]);  // -> plane_xy
    float2 cp1 = __ldg(&cp[1 * n + i]);  // -> plane_yz
    float2 cp2 = __ldg(&cp[2 * n + i]);  // -> plane_xz
    float2 cl0 = __ldg(&cl[0 * n + i]);  // -> line_x
    float2 cl1 = __ldg(&cl[1 * n + i]);  // -> line_y
    float2 cl2 = __ldg(&cl[2 * n + i]);  // -> line_z

    float4 fyz = plane_fetch(g_p[1], cp1, sub);
    float4 fxz = plane_fetch(g_p[2], cp2, sub);
    float4 fxy = plane_fetch(g_p[0], cp0, sub);
    float4 fx  = line_fetch(g_l[0], cl0.y, sub);
    float4 fy  = line_fetch(g_l[1], cl1.y, sub);
    float4 fz  = line_fetch(g_l[2], cl2.y, sub);

    size_t base = (size_t)i * NC + sub * 4;
    float4* out_x = reinterpret_cast<float4*>(out + (size_t)0 * n * NC + base);
    float4* out_y = reinterpret_cast<float4*>(out + (size_t)1 * n * NC + base);
    float4* out_z = reinterpret_cast<float4*>(out + (size_t)2 * n * NC + base);

    *out_x = make_float4(fyz.x * fx.x, fyz.y * fx.y, fyz.z * fx.z, fyz.w * fx.w);
    *out_y = make_float4(fxz.x * fy.x, fxz.y * fy.y, fxz.z * fy.z, fxz.w * fy.w);
    *out_z = make_float4(fxy.x * fz.x, fxy.y * fz.y, fxy.z * fz.z, fxy.w * fz.w);
}

extern "C" void kernel_launch(void* const* d_in, const int* in_sizes, int n_in,
                              void* d_out, int out_size) {
    const float* coords_plane = (const float*)d_in[0];
    const float* coords_line  = (const float*)d_in[1];
    const float* plane_xy     = (const float*)d_in[2];
    const float* plane_yz     = (const float*)d_in[3];
    const float* plane_xz     = (const float*)d_in[4];
    const float* line_x       = (const float*)d_in[5];
    const float* line_y       = (const float*)d_in[6];
    const float* line_z       = (const float*)d_in[7];

    int n = in_sizes[0] / 6;  // coords_plane has 3*N*2 elements

    int t_total = 3 * PLANE_ELEMS + 3 * NP;
    transpose_kernel<<<(t_total + 255) / 256, 256>>>(plane_xy, plane_yz, plane_xz,
                                                     line_x, line_y, line_z);

    long long threads = 4LL * n;
    int blocks = (int)((threads + 255) / 256);
    sample_kernel<<<blocks, 256>>>(
        (const float2*)coords_plane, (const float2*)coords_line,
        (float*)d_out, n);
}